// round 1
// baseline (speedup 1.0000x reference)
#include <cuda_runtime.h>
#include <math.h>

#define H 1024
#define VOCAB 50257

// Scratch (allocation-free rule: __device__ globals)
__device__ float g_x[H];
__device__ float g_h[H];
__device__ float g_c[H];
__device__ float g_gates[4 * H];

// ---------------------------------------------------------------------------
// Embedding row gather: g_x = emb[input_id[0], :]
// ---------------------------------------------------------------------------
__global__ void embed_kernel(const float* __restrict__ emb,
                             const int* __restrict__ id) {
    int row = id[0];
    const float4* src = (const float4*)(emb + (long)row * H);
    float4* dst = (float4*)g_x;
    int i = blockIdx.x * blockDim.x + threadIdx.x;
    if (i < H / 4) dst[i] = src[i];
}

// ---------------------------------------------------------------------------
// gates[r] = dot(W_ih[r], relu(xin)) + dot(W_hh[r], hin) + b_ih[r] + b_hh[r]
// One warp per row; 8 rows per 256-thread block; x/h staged in SMEM.
// ---------------------------------------------------------------------------
__global__ void gemv_gates_kernel(const float* __restrict__ Wih,
                                  const float* __restrict__ Whh,
                                  const float* __restrict__ bih,
                                  const float* __restrict__ bhh,
                                  const float* __restrict__ xin,
                                  const float* __restrict__ hin) {
    __shared__ float sx[H];
    __shared__ float sh[H];
    int t = threadIdx.x;
    for (int i = t; i < H; i += blockDim.x) {
        sx[i] = fmaxf(xin[i], 0.0f);   // relu on the x operand (per reference)
        sh[i] = hin[i];
    }
    __syncthreads();

    int warp = t >> 5, lane = t & 31;
    int row = blockIdx.x * 8 + warp;   // 512 blocks * 8 = 4096 rows
    const float4* wi = (const float4*)(Wih + (long)row * H);
    const float4* wh = (const float4*)(Whh + (long)row * H);
    float acc = 0.f;
#pragma unroll
    for (int k = 0; k < 8; k++) {
        int idx = k * 32 + lane;       // float4 index into the row
        int c0  = idx * 4;
        float4 a = wi[idx];
        acc += a.x * sx[c0] + a.y * sx[c0 + 1] + a.z * sx[c0 + 2] + a.w * sx[c0 + 3];
        float4 b = wh[idx];
        acc += b.x * sh[c0] + b.y * sh[c0 + 1] + b.z * sh[c0 + 2] + b.w * sh[c0 + 3];
    }
#pragma unroll
    for (int o = 16; o > 0; o >>= 1) acc += __shfl_down_sync(0xffffffffu, acc, o);
    if (lane == 0) g_gates[row] = acc + bih[row] + bhh[row];
}

// ---------------------------------------------------------------------------
// LSTM elementwise: torch gate order i, f, g, o
// ---------------------------------------------------------------------------
__global__ void lstm_act_kernel(const float* __restrict__ cin,
                                float* __restrict__ out_tail,
                                int write_tail) {
    int j = threadIdx.x;               // blockDim = 1024
    float ig = g_gates[j];
    float fg = g_gates[j + H];
    float gg = g_gates[j + 2 * H];
    float og = g_gates[j + 3 * H];
    float i_ = 1.f / (1.f + expf(-ig));
    float f_ = 1.f / (1.f + expf(-fg));
    float g_ = tanhf(gg);
    float o_ = 1.f / (1.f + expf(-og));
    float cn = f_ * cin[j] + i_ * g_;
    float hn = o_ * tanhf(cn);
    g_c[j] = cn;
    g_h[j] = hn;
    if (write_tail) {                  // outputs (h, c) after the last step
        out_tail[j]     = hn;
        out_tail[H + j] = cn;
    }
}

// ---------------------------------------------------------------------------
// logits[r] = dot(W_out[r], g_h) + b_out[r]   (the 206MB HBM-bound GEMV)
// ---------------------------------------------------------------------------
__global__ void logits_kernel(const float* __restrict__ Wout,
                              const float* __restrict__ bout,
                              float* __restrict__ out) {
    __shared__ float sh[H];
    int t = threadIdx.x;
    for (int i = t; i < H; i += blockDim.x) sh[i] = g_h[i];
    __syncthreads();

    int warp = t >> 5, lane = t & 31;
    int row = blockIdx.x * 8 + warp;
    if (row >= VOCAB) return;
    const float4* w = (const float4*)(Wout + (long)row * H);
    float acc = 0.f;
#pragma unroll
    for (int k = 0; k < 8; k++) {
        int idx = k * 32 + lane;
        int c0  = idx * 4;
        float4 a = w[idx];
        acc += a.x * sh[c0] + a.y * sh[c0 + 1] + a.z * sh[c0 + 2] + a.w * sh[c0 + 3];
    }
#pragma unroll
    for (int o = 16; o > 0; o >>= 1) acc += __shfl_down_sync(0xffffffffu, acc, o);
    if (lane == 0) out[row] = acc + bout[row];
}

// ---------------------------------------------------------------------------
// In-place log_softmax over out[0:VOCAB], single 1024-thread block.
// ---------------------------------------------------------------------------
__global__ void logsoftmax_kernel(float* __restrict__ out) {
    __shared__ float red[32];
    int t = threadIdx.x;               // blockDim = 1024 (32 warps)
    int lane = t & 31, warp = t >> 5;

    // pass 1: max
    float m = -INFINITY;
    for (int i = t; i < VOCAB; i += 1024) m = fmaxf(m, out[i]);
#pragma unroll
    for (int o = 16; o > 0; o >>= 1) m = fmaxf(m, __shfl_down_sync(0xffffffffu, m, o));
    if (lane == 0) red[warp] = m;
    __syncthreads();
    if (t < 32) {
        m = red[t];
#pragma unroll
        for (int o = 16; o > 0; o >>= 1) m = fmaxf(m, __shfl_down_sync(0xffffffffu, m, o));
        if (t == 0) red[0] = m;
    }
    __syncthreads();
    m = red[0];
    __syncthreads();

    // pass 2: sum exp
    float s = 0.f;
    for (int i = t; i < VOCAB; i += 1024) s += expf(out[i] - m);
#pragma unroll
    for (int o = 16; o > 0; o >>= 1) s += __shfl_down_sync(0xffffffffu, s, o);
    if (lane == 0) red[warp] = s;
    __syncthreads();
    if (t < 32) {
        s = red[t];
#pragma unroll
        for (int o = 16; o > 0; o >>= 1) s += __shfl_down_sync(0xffffffffu, s, o);
        if (t == 0) red[0] = s;
    }
    __syncthreads();
    float lse = m + logf(red[0]);

    // pass 3: write
    for (int i = t; i < VOCAB; i += 1024) out[i] = out[i] - lse;
}

// ---------------------------------------------------------------------------
extern "C" void kernel_launch(void* const* d_in, const int* in_sizes, int n_in,
                              void* d_out, int out_size) {
    const int*   id   = (const int*)d_in[0];
    const float* h0   = (const float*)d_in[1];
    const float* c0   = (const float*)d_in[2];
    const float* emb  = (const float*)d_in[3];
    const float* Wih  = (const float*)d_in[4];
    const float* Whh  = (const float*)d_in[5];
    const float* bih  = (const float*)d_in[6];
    const float* bhh  = (const float*)d_in[7];
    const float* Wout = (const float*)d_in[8];
    const float* bout = (const float*)d_in[9];
    float* out = (float*)d_out;

    float *gx, *gh, *gc;
    cudaGetSymbolAddress((void**)&gx, g_x);
    cudaGetSymbolAddress((void**)&gh, g_h);
    cudaGetSymbolAddress((void**)&gc, g_c);

    int write_tail = (out_size >= VOCAB + 2 * H) ? 1 : 0;

    embed_kernel<<<1, 256>>>(emb, id);

    // step 1: x = relu(emb row), h = h0, c = c0
    gemv_gates_kernel<<<512, 256>>>(Wih, Whh, bih, bhh, gx, h0);
    lstm_act_kernel<<<1, 1024>>>(c0, out + VOCAB, 0);

    // step 2: x = relu(h1), h = h1, c = c1   (same weights, per reference)
    gemv_gates_kernel<<<512, 256>>>(Wih, Whh, bih, bhh, gh, gh);
    lstm_act_kernel<<<1, 1024>>>(gc, out + VOCAB, write_tail);

    // vocab projection + log_softmax (in place over out[0:VOCAB])
    logits_kernel<<<(VOCAB + 7) / 8, 256>>>(Wout, bout, out);
    logsoftmax_kernel<<<1, 1024>>>(out);
}